// round 1
// baseline (speedup 1.0000x reference)
#include <cuda_runtime.h>
#include <cuda_bf16.h>

// SAN Subtraction: out[n,c,kk,p] = x[n,c,h,w] - reflectpad(x)[n,c,h+kh,w+kw]
// N=4, C=64, H=W=112, K=7, PAD=3, STRIDE=1, DIL=1, reflect padding.
// out shape (N, C, 49, 12544), fp32. Output-streaming bound (~630 MB writes).

#define H 112
#define W 112
#define KS 7
#define PADV 3
#define HW (H * W)            // 12544
#define CC 64
#define NN 4

__device__ __forceinline__ int reflect_idx(int j) {
    // numpy 'reflect' (mirror, no edge repeat): j in [-3, 114] -> [0, 111]
    j = j < 0 ? -j : j;
    j = j >= H ? (2 * (H - 1) - j) : j;
    return j;
}

__global__ __launch_bounds__(224) void san_sub_kernel(
    const float* __restrict__ x, float* __restrict__ out)
{
    const int w4 = threadIdx.x << 2;                 // 0,4,...,108
    const int h  = blockIdx.x * 8 + threadIdx.y;     // 0..111
    const int plane = blockIdx.z * CC + blockIdx.y;  // n*64 + c

    const float* xp = x + (size_t)plane * HW;
    float* op = out + (size_t)plane * (KS * KS) * HW + h * W + w4;

    // center (aligned float4: w4 % 4 == 0, row stride 112 floats)
    const float4 ctr = *reinterpret_cast<const float4*>(xp + h * W + w4);

    #pragma unroll
    for (int kh = 0; kh < KS; ++kh) {
        const int rh = reflect_idx(h + kh - PADV);
        const float* row = xp + rh * W;

        // load the 10-wide neighbor span once; reuse across the 7 kw offsets
        float v[10];
        #pragma unroll
        for (int j = 0; j < 10; ++j) {
            const int wi = reflect_idx(w4 - PADV + j);
            v[j] = __ldg(row + wi);
        }

        #pragma unroll
        for (int kw = 0; kw < KS; ++kw) {
            float4 o;
            o.x = ctr.x - v[kw + 0];
            o.y = ctr.y - v[kw + 1];
            o.z = ctr.z - v[kw + 2];
            o.w = ctr.w - v[kw + 3];
            *reinterpret_cast<float4*>(op + (kh * KS + kw) * HW) = o;
        }
    }
}

extern "C" void kernel_launch(void* const* d_in, const int* in_sizes, int n_in,
                              void* d_out, int out_size) {
    const float* x = (const float*)d_in[0];
    float* out = (float*)d_out;
    dim3 block(28, 8, 1);           // 224 threads: 28 float4 spans x 8 rows
    dim3 grid(H / 8, CC, NN);       // (14, 64, 4)
    san_sub_kernel<<<grid, block>>>(x, out);
}